// round 16
// baseline (speedup 1.0000x reference)
#include <cuda_runtime.h>
#include <cuda_fp16.h>
#include <cstdint>
#include <cstddef>

#define TT 64
#define BB 512
#define DD 512
#define HH 2048

// ---------------- scratch (device globals) ---------------------------------
__device__ __align__(16) float  g_ycur[BB * DD];
__device__ __align__(16) float  g_acc [BB * DD];
__device__ __align__(16) __half g_a   [BB * DD];          // gemm1 A operand
__device__ __align__(16) __half g_h   [(size_t)BB * HH];  // hidden activations
__device__ __align__(16) __half g_W1h [(size_t)DD * HH];
__device__ __align__(16) __half g_W2h [(size_t)HH * DD];
__device__ __align__(16) float  g_p1[2][(size_t)BB * HH]; // gemm1 split-K partials
__device__ __align__(16) float  g_p2[8][(size_t)BB * DD]; // gemm2 split-K partials
__device__ int g_cnt1[256];      // per gemm1 tile arrival counter
__device__ int g_cnt2[64];       // per gemm2 tile arrival counter

// ---------------- ptx helpers ----------------------------------------------
__device__ __forceinline__ uint32_t su32(const void* p) {
    return (uint32_t)__cvta_generic_to_shared(p);
}
#define CPA16(d, s) asm volatile("cp.async.cg.shared.global [%0], [%1], 16;" :: "r"(d), "l"(s))
#define CPC()       asm volatile("cp.async.commit_group;" ::: "memory")
#define WAITG(n)    asm volatile("cp.async.wait_group %0;" :: "n"(n) : "memory")

__device__ __forceinline__ void ldsm_x4(uint32_t a[4], uint32_t addr) {
    asm volatile("ldmatrix.sync.aligned.m8n8.x4.shared.b16 {%0,%1,%2,%3}, [%4];"
                 : "=r"(a[0]), "=r"(a[1]), "=r"(a[2]), "=r"(a[3]) : "r"(addr));
}
__device__ __forceinline__ void ldsm_x4_t(uint32_t a[4], uint32_t addr) {
    asm volatile("ldmatrix.sync.aligned.m8n8.x4.trans.shared.b16 {%0,%1,%2,%3}, [%4];"
                 : "=r"(a[0]), "=r"(a[1]), "=r"(a[2]), "=r"(a[3]) : "r"(addr));
}
__device__ __forceinline__ void mma_fp16(float c[4], const uint32_t a[4],
                                         uint32_t b0, uint32_t b1) {
    asm volatile(
        "mma.sync.aligned.m16n8k16.row.col.f32.f16.f16.f32 "
        "{%0,%1,%2,%3},{%4,%5,%6,%7},{%8,%9},{%0,%1,%2,%3};"
        : "+f"(c[0]), "+f"(c[1]), "+f"(c[2]), "+f"(c[3])
        : "r"(a[0]), "r"(a[1]), "r"(a[2]), "r"(a[3]), "r"(b0), "r"(b1));
}

// ---------------- init / convert -------------------------------------------
__global__ void init_state(const float* __restrict__ y0, float* __restrict__ out) {
    int idx = blockIdx.x * blockDim.x + threadIdx.x;
    float4 v = ((const float4*)y0)[idx];
    ((float4*)out)[idx] = v;
    ((float4*)g_ycur)[idx] = v;
    __half2* a2 = (__half2*)g_a;
    a2[idx * 2]     = __floats2half2_rn(v.x, v.y);
    a2[idx * 2 + 1] = __floats2half2_rn(v.z, v.w);
    if (blockIdx.x == 0) {
        if (threadIdx.x < 256) g_cnt1[threadIdx.x] = 0;
        if (threadIdx.x < 64)  g_cnt2[threadIdx.x] = 0;
    }
}
__global__ void convert_w(const float* __restrict__ src, __half* __restrict__ dst) {
    int idx = blockIdx.x * blockDim.x + threadIdx.x;
    float4 v = ((const float4*)src)[idx];
    __half2* d2 = (__half2*)dst;
    d2[idx * 2]     = __floats2half2_rn(v.x, v.y);
    d2[idx * 2 + 1] = __floats2half2_rn(v.z, v.w);
}

extern __shared__ char dyn_sm[];

// ---- common 64x64 / 128-thr / wt 32x32 / BK=32 / 3-stage geometry ----------
#define APIT 40                         // A smem pitch (halves): 32 + 8
#define BPIT 72                         // B smem pitch (halves): 64 + 8
#define ABY  (64 * APIT * 2)            // 5120 B
#define BBY  (32 * BPIT * 2)            // 4608 B
#define STG  (ABY + BBY)                // 9728 B
#define SMEMB (3 * STG)                 // 29184 B

// Last-arriver check (threadFenceReduction pattern; self-resetting counter).
__device__ __forceinline__ bool arrive_last(int* cnt, int need) {
    __shared__ int s_last;
    __syncthreads();
    if (threadIdx.x == 0) {
        __threadfence();
        int old = atomicAdd(cnt, 1);
        s_last = (old == need - 1);
        if (s_last) atomicExch(cnt, 0);
    }
    __syncthreads();
    if (!s_last) return false;
    if (threadIdx.x == 0) __threadfence();
    __syncthreads();
    return true;
}

// ============================================================================
// GEMM1: g_h = tanh(g_a[512x512] @ W1[512x2048] + b1); split-K=2 (K=256/CTA).
// Grid (32, 8, 2) = 512 CTAs.  PDL: W1 prologue pre-sync, A post-sync.
// Last arriver combines p0+p1 (fixed order) + bias + tanh -> g_h, THEN
// triggers (so g_h is visible to the dependent gemm2's post-sync loads).
// ============================================================================
__global__ void __launch_bounds__(128, 4) gemm1_kernel(const float* __restrict__ b1) {
    const int bm = blockIdx.y * 64, bn = blockIdx.x * 64, kz = blockIdx.z;
    const int tile = blockIdx.y * 32 + blockIdx.x;
    const int tid = threadIdx.x, lane = tid & 31, warp = tid >> 5;
    const int g = lane >> 2, tg = lane & 3;
    const int wm = (warp >> 1) * 32, wn = (warp & 1) * 32;
    const int l16 = lane & 15, h16 = (lane >> 4) * 8;

    const __half* Ag = g_a + (size_t)bm * DD + kz * 256;
    const __half* Bg = g_W1h + (size_t)(kz * 256) * HH + bn;

    auto loadA = [&](int st, int kt) {
        char* Ab = dyn_sm + st * STG;
#pragma unroll
        for (int l = 0; l < 2; l++) {
            int j = tid + l * 128, r = j >> 2, c = (j & 3) * 8;
            CPA16(su32(Ab + (r * APIT + c) * 2), Ag + (size_t)r * DD + kt * 32 + c);
        }
    };
    auto loadB = [&](int st, int kt) {
        char* Bb = dyn_sm + st * STG + ABY;
#pragma unroll
        for (int l = 0; l < 2; l++) {
            int j = tid + l * 128, r = j >> 3, c = (j & 7) * 8;
            CPA16(su32(Bb + (r * BPIT + c) * 2), Bg + (size_t)(kt * 32 + r) * HH + c);
        }
    };
    auto loadStage = [&](int st, int kt) { loadA(st, kt); loadB(st, kt); CPC(); };
    auto ldfA = [&](uint32_t Af[2][4], int st, int ks) {
        char* Ab = dyn_sm + st * STG;
#pragma unroll
        for (int mi = 0; mi < 2; mi++)
            ldsm_x4(Af[mi], su32(Ab + ((wm + mi * 16 + l16) * APIT + ks + h16) * 2));
    };
    auto ldfB = [&](uint32_t Bf[4][2], int st, int ks) {
        char* Bb = dyn_sm + st * STG + ABY;
#pragma unroll
        for (int bt = 0; bt < 2; bt++) {
            uint32_t r[4];
            ldsm_x4_t(r, su32(Bb + ((ks + l16) * BPIT + wn + bt * 16 + h16) * 2));
            Bf[bt * 2][0] = r[0]; Bf[bt * 2][1] = r[1];
            Bf[bt * 2 + 1][0] = r[2]; Bf[bt * 2 + 1][1] = r[3];
        }
    };

    // PDL prologue: weights first (independent of producer), A after the sync.
    loadB(0, 0); loadB(1, 1); loadB(2, 2);
    cudaGridDependencySynchronize();
    loadA(0, 0); CPC();
    loadA(1, 1); CPC();
    loadA(2, 2); CPC();
    WAITG(2);
    __syncthreads();

    float acc[2][4][4];
#pragma unroll
    for (int mi = 0; mi < 2; mi++)
#pragma unroll
        for (int ni = 0; ni < 4; ni++)
#pragma unroll
            for (int r = 0; r < 4; r++) acc[mi][ni][r] = 0.f;

    uint32_t Af[2][2][4], Bf[2][4][2];
    ldfA(Af[0], 0, 0); ldfB(Bf[0], 0, 0);

    for (int kt = 0; kt < 8; kt++) {
        const int st = kt % 3;
#pragma unroll
        for (int ks = 0; ks < 2; ks++) {
            const int pb = ks & 1;
            if (ks == 1) { WAITG(1); __syncthreads(); }
            const int nst = (ks == 0) ? st : ((kt + 1) % 3);
            const int nks = (ks == 0) ? 16 : 0;
            if (ks == 0 || kt + 1 < 8) {
                ldfA(Af[pb ^ 1], nst, nks);
                ldfB(Bf[pb ^ 1], nst, nks);
            }
#pragma unroll
            for (int mi = 0; mi < 2; mi++)
#pragma unroll
                for (int ni = 0; ni < 4; ni++)
                    mma_fp16(acc[mi][ni], Af[pb][mi], Bf[pb][ni][0], Bf[pb][ni][1]);
        }
        if (kt + 3 < 8) loadStage((kt + 3) % 3, kt + 3); else CPC();
    }

    // publish fp32 partial (column-space pitch HH)
    {
        float* dst = g_p1[kz];
#pragma unroll
        for (int mi = 0; mi < 2; mi++)
#pragma unroll
            for (int ni = 0; ni < 4; ni++) {
                int col = bn + wn + ni * 8 + tg * 2;
#pragma unroll
                for (int hr = 0; hr < 2; hr++) {
                    int row = bm + wm + mi * 16 + g + hr * 8;
                    *(float2*)&dst[(size_t)row * HH + col] =
                        make_float2(acc[mi][ni][hr * 2 + 0], acc[mi][ni][hr * 2 + 1]);
                }
            }
    }
    if (!arrive_last(&g_cnt1[tile], 2)) {
        cudaTriggerProgrammaticLaunchCompletion();   // no post-trigger global writes
        return;
    }

    // combine p0 + p1 (fixed order) + bias, tanh, write g_h
#pragma unroll
    for (int q = 0; q < 4; q++) {
        int row = bm + (tid >> 3) + q * 16;
        int col = bn + (tid & 7) * 8;
        size_t off = (size_t)row * HH + col;
        float4 a0 = *(const float4*)&g_p1[0][off];
        float4 a1 = *(const float4*)&g_p1[0][off + 4];
        float4 c0 = *(const float4*)&g_p1[1][off];
        float4 c1 = *(const float4*)&g_p1[1][off + 4];
        float4 bb0 = *(const float4*)(b1 + col);
        float4 bb1 = *(const float4*)(b1 + col + 4);
        uint4 o;
        __half2 h;
        h = __floats2half2_rn(tanhf(a0.x + c0.x + bb0.x), tanhf(a0.y + c0.y + bb0.y));
        __builtin_memcpy(&o.x, &h, 4);
        h = __floats2half2_rn(tanhf(a0.z + c0.z + bb0.z), tanhf(a0.w + c0.w + bb0.w));
        __builtin_memcpy(&o.y, &h, 4);
        h = __floats2half2_rn(tanhf(a1.x + c1.x + bb1.x), tanhf(a1.y + c1.y + bb1.y));
        __builtin_memcpy(&o.z, &h, 4);
        h = __floats2half2_rn(tanhf(a1.z + c1.z + bb1.z), tanhf(a1.w + c1.w + bb1.w));
        __builtin_memcpy(&o.w, &h, 4);
        *(uint4*)&g_h[off] = o;
    }
    // g_h written -> now safe to let the dependent kernel's post-sync loads go.
    cudaTriggerProgrammaticLaunchCompletion();
}

// ============================================================================
// GEMM2: C = g_h[512x2048] @ W2[2048x512]; split-K=8 (K=256/CTA).
// Grid (8, 8, 8) = 512 CTAs.  PDL: W2 prologue pre-sync, A post-sync.
// Last arriver: fixed-order combine + RK4 epilogue, trigger AFTER g_a writes.
// ============================================================================
__global__ void __launch_bounds__(128, 4) gemm2_kernel(const float* __restrict__ b2,
                                                       const float* __restrict__ tarr,
                                                       float* __restrict__ out,
                                                       int s, float wgt, float cnext,
                                                       int first, int last) {
    const int bm = blockIdx.y * 64, bn = blockIdx.x * 64, kz = blockIdx.z;
    const int tile = blockIdx.y * 8 + blockIdx.x;
    const int tid = threadIdx.x, lane = tid & 31, warp = tid >> 5;
    const int g = lane >> 2, tg = lane & 3;
    const int wm = (warp >> 1) * 32, wn = (warp & 1) * 32;
    const int l16 = lane & 15, h16 = (lane >> 4) * 8;

    const __half* Ag = g_h + (size_t)bm * HH + kz * 256;
    const __half* Bg = g_W2h + (size_t)(kz * 256) * DD + bn;

    auto loadA = [&](int st, int kt) {
        char* Ab = dyn_sm + st * STG;
#pragma unroll
        for (int l = 0; l < 2; l++) {
            int j = tid + l * 128, r = j >> 2, c = (j & 3) * 8;
            CPA16(su32(Ab + (r * APIT + c) * 2), Ag + (size_t)r * HH + kt * 32 + c);
        }
    };
    auto loadB = [&](int st, int kt) {
        char* Bb = dyn_sm + st * STG + ABY;
#pragma unroll
        for (int l = 0; l < 2; l++) {
            int j = tid + l * 128, r = j >> 3, c = (j & 7) * 8;
            CPA16(su32(Bb + (r * BPIT + c) * 2), Bg + (size_t)(kt * 32 + r) * DD + c);
        }
    };
    auto loadStage = [&](int st, int kt) { loadA(st, kt); loadB(st, kt); CPC(); };
    auto ldfA = [&](uint32_t Af[2][4], int st, int ks) {
        char* Ab = dyn_sm + st * STG;
#pragma unroll
        for (int mi = 0; mi < 2; mi++)
            ldsm_x4(Af[mi], su32(Ab + ((wm + mi * 16 + l16) * APIT + ks + h16) * 2));
    };
    auto ldfB = [&](uint32_t Bf[4][2], int st, int ks) {
        char* Bb = dyn_sm + st * STG + ABY;
#pragma unroll
        for (int bt = 0; bt < 2; bt++) {
            uint32_t r[4];
            ldsm_x4_t(r, su32(Bb + ((ks + l16) * BPIT + wn + bt * 16 + h16) * 2));
            Bf[bt * 2][0] = r[0]; Bf[bt * 2][1] = r[1];
            Bf[bt * 2 + 1][0] = r[2]; Bf[bt * 2 + 1][1] = r[3];
        }
    };

    // PDL prologue: weights first, A (g_h from gemm1) after the dependency.
    loadB(0, 0); loadB(1, 1); loadB(2, 2);
    cudaGridDependencySynchronize();
    loadA(0, 0); CPC();
    loadA(1, 1); CPC();
    loadA(2, 2); CPC();
    WAITG(2);
    __syncthreads();

    float acc[2][4][4];
#pragma unroll
    for (int mi = 0; mi < 2; mi++)
#pragma unroll
        for (int ni = 0; ni < 4; ni++)
#pragma unroll
            for (int r = 0; r < 4; r++) acc[mi][ni][r] = 0.f;

    uint32_t Af[2][2][4], Bf[2][4][2];
    ldfA(Af[0], 0, 0); ldfB(Bf[0], 0, 0);

    for (int kt = 0; kt < 8; kt++) {
        const int st = kt % 3;
#pragma unroll
        for (int ks = 0; ks < 2; ks++) {
            const int pb = ks & 1;
            if (ks == 1) { WAITG(1); __syncthreads(); }
            const int nst = (ks == 0) ? st : ((kt + 1) % 3);
            const int nks = (ks == 0) ? 16 : 0;
            if (ks == 0 || kt + 1 < 8) {
                ldfA(Af[pb ^ 1], nst, nks);
                ldfB(Bf[pb ^ 1], nst, nks);
            }
#pragma unroll
            for (int mi = 0; mi < 2; mi++)
#pragma unroll
                for (int ni = 0; ni < 4; ni++)
                    mma_fp16(acc[mi][ni], Af[pb][mi], Bf[pb][ni][0], Bf[pb][ni][1]);
        }
        if (kt + 3 < 8) loadStage((kt + 3) % 3, kt + 3); else CPC();
    }

    // publish partial
    {
        float* dst = g_p2[kz];
#pragma unroll
        for (int mi = 0; mi < 2; mi++)
#pragma unroll
            for (int ni = 0; ni < 4; ni++) {
                int col = bn + wn + ni * 8 + tg * 2;
#pragma unroll
                for (int hr = 0; hr < 2; hr++) {
                    int row = bm + wm + mi * 16 + g + hr * 8;
                    *(float2*)&dst[(size_t)row * DD + col] =
                        make_float2(acc[mi][ni][hr * 2 + 0], acc[mi][ni][hr * 2 + 1]);
                }
            }
    }
    if (!arrive_last(&g_cnt2[tile], 8)) {
        cudaTriggerProgrammaticLaunchCompletion();   // no post-trigger global writes
        return;
    }

    // combine + RK4 epilogue (128 thr x 32 elems over the 64x64 tile)
    const float inv6 = 1.0f / 6.0f;
#pragma unroll
    for (int q = 0; q < 4; q++) {
        int row = bm + (tid >> 3) + q * 16;
        int col = bn + (tid & 7) * 8;
        size_t off = (size_t)row * DD + col;
        float dt = __ldg(tarr + (size_t)(s + 1) * BB + row)
                 - __ldg(tarr + (size_t)s * BB + row);

        float sum[8];
        {
            float4 a = *(const float4*)&g_p2[0][off];
            float4 b = *(const float4*)&g_p2[0][off + 4];
            sum[0] = a.x; sum[1] = a.y; sum[2] = a.z; sum[3] = a.w;
            sum[4] = b.x; sum[5] = b.y; sum[6] = b.z; sum[7] = b.w;
        }
#pragma unroll
        for (int z = 1; z < 8; z++) {
            float4 a = *(const float4*)&g_p2[z][off];
            float4 b = *(const float4*)&g_p2[z][off + 4];
            sum[0] += a.x; sum[1] += a.y; sum[2] += a.z; sum[3] += a.w;
            sum[4] += b.x; sum[5] += b.y; sum[6] += b.z; sum[7] += b.w;
        }

        float kv[8];
#pragma unroll
        for (int e = 0; e < 8; e++)
            kv[e] = dt * (sum[e] + __ldg(b2 + col + e));

        float yc[8], av[8];
        *(float4*)&yc[0] = *(const float4*)&g_ycur[off];
        *(float4*)&yc[4] = *(const float4*)&g_ycur[off + 4];
        if (first) {
#pragma unroll
            for (int e = 0; e < 8; e++) av[e] = wgt * kv[e];
        } else {
            *(float4*)&av[0] = *(const float4*)&g_acc[off];
            *(float4*)&av[4] = *(const float4*)&g_acc[off + 4];
#pragma unroll
            for (int e = 0; e < 8; e++) av[e] += wgt * kv[e];
        }

        uint4 ah;
        if (!last) {
            *(float4*)&g_acc[off]     = *(const float4*)&av[0];
            *(float4*)&g_acc[off + 4] = *(const float4*)&av[4];
            __half2 h;
            h = __floats2half2_rn(yc[0] + cnext * kv[0], yc[1] + cnext * kv[1]);
            __builtin_memcpy(&ah.x, &h, 4);
            h = __floats2half2_rn(yc[2] + cnext * kv[2], yc[3] + cnext * kv[3]);
            __builtin_memcpy(&ah.y, &h, 4);
            h = __floats2half2_rn(yc[4] + cnext * kv[4], yc[5] + cnext * kv[5]);
            __builtin_memcpy(&ah.z, &h, 4);
            h = __floats2half2_rn(yc[6] + cnext * kv[6], yc[7] + cnext * kv[7]);
            __builtin_memcpy(&ah.w, &h, 4);
        } else {
            float yn[8];
#pragma unroll
            for (int e = 0; e < 8; e++) yn[e] = yc[e] + av[e] * inv6;
            *(float4*)&g_ycur[off]     = *(const float4*)&yn[0];
            *(float4*)&g_ycur[off + 4] = *(const float4*)&yn[4];
            *(float4*)&out[(size_t)(s + 1) * BB * DD + off]     = *(const float4*)&yn[0];
            *(float4*)&out[(size_t)(s + 1) * BB * DD + off + 4] = *(const float4*)&yn[4];
            __half2 h;
            h = __floats2half2_rn(yn[0], yn[1]); __builtin_memcpy(&ah.x, &h, 4);
            h = __floats2half2_rn(yn[2], yn[3]); __builtin_memcpy(&ah.y, &h, 4);
            h = __floats2half2_rn(yn[4], yn[5]); __builtin_memcpy(&ah.z, &h, 4);
            h = __floats2half2_rn(yn[6], yn[7]); __builtin_memcpy(&ah.w, &h, 4);
        }
        *(uint4*)&g_a[off] = ah;
    }
    // g_a / g_acc / g_ycur / out written -> now legal to release the dependent.
    cudaTriggerProgrammaticLaunchCompletion();
}

// ---------------------------------------------------------------------------
extern "C" void kernel_launch(void* const* d_in, const int* in_sizes, int n_in,
                              void* d_out, int out_size) {
    const float* y0 = (const float*)d_in[0];
    const float* t  = (const float*)d_in[1];
    const float* W1 = (const float*)d_in[2];
    const float* b1 = (const float*)d_in[3];
    const float* W2 = (const float*)d_in[4];
    const float* b2 = (const float*)d_in[5];
    float* out = (float*)d_out;

    cudaFuncSetAttribute(gemm1_kernel, cudaFuncAttributeMaxDynamicSharedMemorySize, SMEMB);
    cudaFuncSetAttribute(gemm2_kernel, cudaFuncAttributeMaxDynamicSharedMemorySize, SMEMB);

    __half* w1h; cudaGetSymbolAddress((void**)&w1h, g_W1h);
    __half* w2h; cudaGetSymbolAddress((void**)&w2h, g_W2h);

    init_state<<<(BB * DD / 4) / 256, 256>>>(y0, out);
    convert_w<<<(DD * HH / 4) / 256, 256>>>(W1, w1h);
    convert_w<<<(HH * DD / 4) / 256, 256>>>(W2, w2h);

    const float ws[4] = {1.0f, 2.0f, 2.0f, 1.0f};
    const float cn[4] = {0.5f, 0.5f, 1.0f, 0.0f};

    dim3 grid1(HH / 64, BB / 64, 2);   // 32 x 8 x 2 = 512 CTAs
    dim3 grid2(DD / 64, BB / 64, 8);   // 8 x 8 x 8  = 512 CTAs

    cudaLaunchAttribute pdl[1];
    pdl[0].id = cudaLaunchAttributeProgrammaticStreamSerialization;
    pdl[0].val.programmaticStreamSerializationAllowed = 1;

    cudaLaunchConfig_t cfg1 = {};
    cfg1.gridDim = grid1; cfg1.blockDim = dim3(128, 1, 1);
    cfg1.dynamicSmemBytes = SMEMB;
    cfg1.attrs = pdl; cfg1.numAttrs = 1;

    cudaLaunchConfig_t cfg2 = {};
    cfg2.gridDim = grid2; cfg2.blockDim = dim3(128, 1, 1);
    cfg2.dynamicSmemBytes = SMEMB;
    cfg2.attrs = pdl; cfg2.numAttrs = 1;

    for (int s = 0; s < TT - 1; ++s) {
        for (int i = 0; i < 4; ++i) {
            if (s == 0 && i == 0) {
                // first gemm1: producer convert_w writes W1h, which is read in
                // the PRE-sync prologue -> must launch fully serialized.
                gemm1_kernel<<<grid1, 128, SMEMB>>>(b1);
            } else {
                cudaLaunchKernelEx(&cfg1, gemm1_kernel, b1);
            }
            cudaLaunchKernelEx(&cfg2, gemm2_kernel, b2, t, out, s, ws[i], cn[i],
                               (i == 0) ? 1 : 0, (i == 3) ? 1 : 0);
        }
    }
}

// round 17
// speedup vs baseline: 1.1754x; 1.1754x over previous
#include <cuda_runtime.h>
#include <cuda_fp16.h>
#include <cstdint>
#include <cstddef>

#define TT 64
#define BB 512
#define DD 512
#define HH 2048

// ---------------- scratch (device globals) ---------------------------------
__device__ __align__(16) float  g_ycur[BB * DD];
__device__ __align__(16) float  g_acc [BB * DD];
__device__ __align__(16) __half g_a   [BB * DD];          // gemm1 A operand
__device__ __align__(16) __half g_h   [(size_t)BB * HH];  // hidden activations
__device__ __align__(16) __half g_W1h [(size_t)DD * HH];
__device__ __align__(16) __half g_W2h [(size_t)HH * DD];
__device__ __align__(16) float  g_p2[8][(size_t)BB * DD]; // gemm2 split-K partials
__device__ int g_cnt2[64];       // per gemm2 tile arrival counter

// ---------------- ptx helpers ----------------------------------------------
__device__ __forceinline__ uint32_t su32(const void* p) {
    return (uint32_t)__cvta_generic_to_shared(p);
}
#define CPA16(d, s) asm volatile("cp.async.cg.shared.global [%0], [%1], 16;" :: "r"(d), "l"(s))
#define CPC()       asm volatile("cp.async.commit_group;" ::: "memory")
#define WAITG(n)    asm volatile("cp.async.wait_group %0;" :: "n"(n) : "memory")
#define NBAR(id)    asm volatile("bar.sync %0, 128;" :: "r"(id) : "memory")

__device__ __forceinline__ void ldsm_x4(uint32_t a[4], uint32_t addr) {
    asm volatile("ldmatrix.sync.aligned.m8n8.x4.shared.b16 {%0,%1,%2,%3}, [%4];"
                 : "=r"(a[0]), "=r"(a[1]), "=r"(a[2]), "=r"(a[3]) : "r"(addr));
}
__device__ __forceinline__ void ldsm_x4_t(uint32_t a[4], uint32_t addr) {
    asm volatile("ldmatrix.sync.aligned.m8n8.x4.trans.shared.b16 {%0,%1,%2,%3}, [%4];"
                 : "=r"(a[0]), "=r"(a[1]), "=r"(a[2]), "=r"(a[3]) : "r"(addr));
}
__device__ __forceinline__ void mma_fp16(float c[4], const uint32_t a[4],
                                         uint32_t b0, uint32_t b1) {
    asm volatile(
        "mma.sync.aligned.m16n8k16.row.col.f32.f16.f16.f32 "
        "{%0,%1,%2,%3},{%4,%5,%6,%7},{%8,%9},{%0,%1,%2,%3};"
        : "+f"(c[0]), "+f"(c[1]), "+f"(c[2]), "+f"(c[3])
        : "r"(a[0]), "r"(a[1]), "r"(a[2]), "r"(a[3]), "r"(b0), "r"(b1));
}

// ---------------- init / convert -------------------------------------------
__global__ void init_state(const float* __restrict__ y0, float* __restrict__ out) {
    int idx = blockIdx.x * blockDim.x + threadIdx.x;
    float4 v = ((const float4*)y0)[idx];
    ((float4*)out)[idx] = v;
    ((float4*)g_ycur)[idx] = v;
    __half2* a2 = (__half2*)g_a;
    a2[idx * 2]     = __floats2half2_rn(v.x, v.y);
    a2[idx * 2 + 1] = __floats2half2_rn(v.z, v.w);
    if (blockIdx.x == 0 && threadIdx.x < 64) g_cnt2[threadIdx.x] = 0;
}
__global__ void convert_w(const float* __restrict__ src, __half* __restrict__ dst) {
    int idx = blockIdx.x * blockDim.x + threadIdx.x;
    float4 v = ((const float4*)src)[idx];
    __half2* d2 = (__half2*)dst;
    d2[idx * 2]     = __floats2half2_rn(v.x, v.y);
    d2[idx * 2 + 1] = __floats2half2_rn(v.z, v.w);
}

extern __shared__ char dyn_sm[];

// ---- common domain geometry: 64x64 out, K=256, 4 warps, BK=32, 3-stage -----
#define APIT 40                         // A smem pitch (halves): 32 + 8
#define BPIT 72                         // B smem pitch (halves): 64 + 8
#define ABY  (64 * APIT * 2)            // 5120 B
#define BBY  (32 * BPIT * 2)            // 4608 B
#define STG  (ABY + BBY)                // 9728 B per stage
#define DSTG3 (3 * STG)                 // 29184 B per domain
#define SMEM1 (4 * DSTG3)               // 116736 B (gemm1: 4 domains)
#define SMEM2 DSTG3                     // 29184 B (gemm2: 1 domain per CTA)
#define RED_PIT 68                      // smem reduction pitch (floats)

// ============================================================================
// GEMM1: g_h = tanh(g_a[512x512] @ W1[512x2048] + b1)
// CTA 64x128 tile, 512 thr = 4 INDEPENDENT domains of 4 warps, each a 64x64 x
// K=256 pipeline with its own smem stages + named barrier (emulates 4
// co-resident gemm2-shaped CTAs per SM).  dom = nd*2 + kd:
//   nd = N-half (cols 0-63 / 64-127), kd = K-half (0-255 / 256-511).
// K-halves combine via smem (kd1 -> kd0), then bias + tanh -> g_h.
// Grid (16, 8) = 128 CTAs.  PDL: W1 pre-sync, A post-sync.
// ============================================================================
__global__ void __launch_bounds__(512, 1) gemm1_kernel(const float* __restrict__ b1) {
    const int tid = threadIdx.x, lane = tid & 31, warp = tid >> 5;
    const int g = lane >> 2, tg = lane & 3;
    const int dom = warp >> 2, w4 = warp & 3;
    const int nd = dom >> 1, kd = dom & 1;
    const int wm = (w4 >> 1) * 32, wn = (w4 & 1) * 32;
    const int dtid = tid & 127;
    const int l16 = lane & 15, h16 = (lane >> 4) * 8;
    const int bm = blockIdx.y * 64, bn = blockIdx.x * 128 + nd * 64;
    const int bar = dom + 1;

    char* dbase = dyn_sm + dom * DSTG3;
    const __half* Ag = g_a + (size_t)bm * DD + kd * 256;
    const __half* Bg = g_W1h + (size_t)(kd * 256) * HH + bn;

    auto loadA = [&](int st, int kt) {
        char* Ab = dbase + st * STG;
#pragma unroll
        for (int l = 0; l < 2; l++) {
            int j = dtid + l * 128, r = j >> 2, c = (j & 3) * 8;
            CPA16(su32(Ab + (r * APIT + c) * 2), Ag + (size_t)r * DD + kt * 32 + c);
        }
    };
    auto loadB = [&](int st, int kt) {
        char* Bb = dbase + st * STG + ABY;
#pragma unroll
        for (int l = 0; l < 2; l++) {
            int j = dtid + l * 128, r = j >> 3, c = (j & 7) * 8;
            CPA16(su32(Bb + (r * BPIT + c) * 2), Bg + (size_t)(kt * 32 + r) * HH + c);
        }
    };
    auto loadStage = [&](int st, int kt) { loadA(st, kt); loadB(st, kt); CPC(); };
    auto ldfA = [&](uint32_t Af[2][4], int st, int ks) {
        char* Ab = dbase + st * STG;
#pragma unroll
        for (int mi = 0; mi < 2; mi++)
            ldsm_x4(Af[mi], su32(Ab + ((wm + mi * 16 + l16) * APIT + ks + h16) * 2));
    };
    auto ldfB = [&](uint32_t Bf[4][2], int st, int ks) {
        char* Bb = dbase + st * STG + ABY;
#pragma unroll
        for (int bt = 0; bt < 2; bt++) {
            uint32_t r[4];
            ldsm_x4_t(r, su32(Bb + ((ks + l16) * BPIT + wn + bt * 16 + h16) * 2));
            Bf[bt * 2][0] = r[0]; Bf[bt * 2][1] = r[1];
            Bf[bt * 2 + 1][0] = r[2]; Bf[bt * 2 + 1][1] = r[3];
        }
    };

    // PDL prologue: weights first (independent of producer), A after the sync.
    loadB(0, 0); loadB(1, 1); loadB(2, 2);
    cudaGridDependencySynchronize();
    loadA(0, 0); CPC();
    loadA(1, 1); CPC();
    loadA(2, 2); CPC();
    WAITG(2);
    NBAR(bar);

    float acc[2][4][4];
#pragma unroll
    for (int mi = 0; mi < 2; mi++)
#pragma unroll
        for (int ni = 0; ni < 4; ni++)
#pragma unroll
            for (int r = 0; r < 4; r++) acc[mi][ni][r] = 0.f;

    uint32_t Af[2][2][4], Bf[2][4][2];
    ldfA(Af[0], 0, 0); ldfB(Bf[0], 0, 0);

    for (int kt = 0; kt < 8; kt++) {
        const int st = kt % 3;
#pragma unroll
        for (int ks = 0; ks < 2; ks++) {
            const int pb = ks & 1;
            if (ks == 1) { WAITG(1); NBAR(bar); }
            const int nst = (ks == 0) ? st : ((kt + 1) % 3);
            const int nks = (ks == 0) ? 16 : 0;
            if (ks == 0 || kt + 1 < 8) {
                ldfA(Af[pb ^ 1], nst, nks);
                ldfB(Bf[pb ^ 1], nst, nks);
            }
#pragma unroll
            for (int mi = 0; mi < 2; mi++)
#pragma unroll
                for (int ni = 0; ni < 4; ni++)
                    mma_fp16(acc[mi][ni], Af[pb][mi], Bf[pb][ni][0], Bf[pb][ni][1]);
        }
        if (kt + 3 < 8) loadStage((kt + 3) % 3, kt + 3); else CPC();
    }

    // drain own cp.asyncs, then reuse this domain's stage smem as fp32 red buf
    WAITG(0);
    NBAR(bar);
    {
        float* redw = (float*)dbase;      // 64 x RED_PIT fp32 = 17408 B < 29184
#pragma unroll
        for (int mi = 0; mi < 2; mi++)
#pragma unroll
            for (int ni = 0; ni < 4; ni++) {
                int col = wn + ni * 8 + tg * 2;
#pragma unroll
                for (int hr = 0; hr < 2; hr++) {
                    int row = wm + mi * 16 + g + hr * 8;
                    *(float2*)&redw[row * RED_PIT + col] =
                        make_float2(acc[mi][ni][hr * 2 + 0], acc[mi][ni][hr * 2 + 1]);
                }
            }
    }
    __syncthreads();   // cross-domain: kd1 partials visible to kd0

    if (kd == 0) {
        const float* r0 = (const float*)(dyn_sm + dom * DSTG3);
        const float* r1 = (const float*)(dyn_sm + (dom + 1) * DSTG3);
#pragma unroll
        for (int q = 0; q < 4; q++) {
            int rl = (dtid >> 3) + q * 16;
            int cl = (dtid & 7) * 8;
            int base = rl * RED_PIT + cl;
            float4 a0 = *(const float4*)&r0[base];
            float4 a1 = *(const float4*)&r0[base + 4];
            float4 c0 = *(const float4*)&r1[base];
            float4 c1 = *(const float4*)&r1[base + 4];
            float4 bb0 = *(const float4*)(b1 + bn + cl);
            float4 bb1 = *(const float4*)(b1 + bn + cl + 4);
            uint4 o;
            __half2 h;
            h = __floats2half2_rn(tanhf(a0.x + c0.x + bb0.x), tanhf(a0.y + c0.y + bb0.y));
            __builtin_memcpy(&o.x, &h, 4);
            h = __floats2half2_rn(tanhf(a0.z + c0.z + bb0.z), tanhf(a0.w + c0.w + bb0.w));
            __builtin_memcpy(&o.y, &h, 4);
            h = __floats2half2_rn(tanhf(a1.x + c1.x + bb1.x), tanhf(a1.y + c1.y + bb1.y));
            __builtin_memcpy(&o.z, &h, 4);
            h = __floats2half2_rn(tanhf(a1.z + c1.z + bb1.z), tanhf(a1.w + c1.w + bb1.w));
            __builtin_memcpy(&o.w, &h, 4);
            *(uint4*)&g_h[(size_t)(bm + rl) * HH + bn + cl] = o;
        }
    }
    // g_h written (all CTA writes done before any thread triggers? trigger is
    // per-CTA released when all threads reach it; kd1 threads reach it early
    // but the dependent launch waits for ALL CTAs' triggers, and kd0 threads
    // trigger only after their g_h stores).
    cudaTriggerProgrammaticLaunchCompletion();
}

// ============================================================================
// GEMM2: C = g_h[512x2048] @ W2[2048x512]; split-K=8 (K=256/CTA).
// Grid (8, 8, 8) = 512 CTAs.  CTA 64x64, 128 thr, wt 32x32, BK=32, 3-stage.
// PDL: W2 pre-sync, A post-sync.  Last arriver: fixed-order combine + RK4,
// trigger AFTER the g_a/g_ycur/out writes.
// ============================================================================
__global__ void __launch_bounds__(128, 4) gemm2_kernel(const float* __restrict__ b2,
                                                       const float* __restrict__ tarr,
                                                       float* __restrict__ out,
                                                       int s, float wgt, float cnext,
                                                       int first, int last) {
    const int bm = blockIdx.y * 64, bn = blockIdx.x * 64, kz = blockIdx.z;
    const int tile = blockIdx.y * 8 + blockIdx.x;
    const int tid = threadIdx.x, lane = tid & 31, warp = tid >> 5;
    const int g = lane >> 2, tg = lane & 3;
    const int wm = (warp >> 1) * 32, wn = (warp & 1) * 32;
    const int l16 = lane & 15, h16 = (lane >> 4) * 8;

    const __half* Ag = g_h + (size_t)bm * HH + kz * 256;
    const __half* Bg = g_W2h + (size_t)(kz * 256) * DD + bn;

    auto loadA = [&](int st, int kt) {
        char* Ab = dyn_sm + st * STG;
#pragma unroll
        for (int l = 0; l < 2; l++) {
            int j = tid + l * 128, r = j >> 2, c = (j & 3) * 8;
            CPA16(su32(Ab + (r * APIT + c) * 2), Ag + (size_t)r * HH + kt * 32 + c);
        }
    };
    auto loadB = [&](int st, int kt) {
        char* Bb = dyn_sm + st * STG + ABY;
#pragma unroll
        for (int l = 0; l < 2; l++) {
            int j = tid + l * 128, r = j >> 3, c = (j & 7) * 8;
            CPA16(su32(Bb + (r * BPIT + c) * 2), Bg + (size_t)(kt * 32 + r) * DD + c);
        }
    };
    auto loadStage = [&](int st, int kt) { loadA(st, kt); loadB(st, kt); CPC(); };
    auto ldfA = [&](uint32_t Af[2][4], int st, int ks) {
        char* Ab = dyn_sm + st * STG;
#pragma unroll
        for (int mi = 0; mi < 2; mi++)
            ldsm_x4(Af[mi], su32(Ab + ((wm + mi * 16 + l16) * APIT + ks + h16) * 2));
    };
    auto ldfB = [&](uint32_t Bf[4][2], int st, int ks) {
        char* Bb = dyn_sm + st * STG + ABY;
#pragma unroll
        for (int bt = 0; bt < 2; bt++) {
            uint32_t r[4];
            ldsm_x4_t(r, su32(Bb + ((ks + l16) * BPIT + wn + bt * 16 + h16) * 2));
            Bf[bt * 2][0] = r[0]; Bf[bt * 2][1] = r[1];
            Bf[bt * 2 + 1][0] = r[2]; Bf[bt * 2 + 1][1] = r[3];
        }
    };

    // PDL prologue: weights first, A (g_h from gemm1) after the dependency.
    loadB(0, 0); loadB(1, 1); loadB(2, 2);
    cudaGridDependencySynchronize();
    loadA(0, 0); CPC();
    loadA(1, 1); CPC();
    loadA(2, 2); CPC();
    WAITG(2);
    __syncthreads();

    float acc[2][4][4];
#pragma unroll
    for (int mi = 0; mi < 2; mi++)
#pragma unroll
        for (int ni = 0; ni < 4; ni++)
#pragma unroll
            for (int r = 0; r < 4; r++) acc[mi][ni][r] = 0.f;

    uint32_t Af[2][2][4], Bf[2][4][2];
    ldfA(Af[0], 0, 0); ldfB(Bf[0], 0, 0);

    for (int kt = 0; kt < 8; kt++) {
        const int st = kt % 3;
#pragma unroll
        for (int ks = 0; ks < 2; ks++) {
            const int pb = ks & 1;
            if (ks == 1) { WAITG(1); __syncthreads(); }
            const int nst = (ks == 0) ? st : ((kt + 1) % 3);
            const int nks = (ks == 0) ? 16 : 0;
            if (ks == 0 || kt + 1 < 8) {
                ldfA(Af[pb ^ 1], nst, nks);
                ldfB(Bf[pb ^ 1], nst, nks);
            }
#pragma unroll
            for (int mi = 0; mi < 2; mi++)
#pragma unroll
                for (int ni = 0; ni < 4; ni++)
                    mma_fp16(acc[mi][ni], Af[pb][mi], Bf[pb][ni][0], Bf[pb][ni][1]);
        }
        if (kt + 3 < 8) loadStage((kt + 3) % 3, kt + 3); else CPC();
    }

    // publish partial
    {
        float* dst = g_p2[kz];
#pragma unroll
        for (int mi = 0; mi < 2; mi++)
#pragma unroll
            for (int ni = 0; ni < 4; ni++) {
                int col = bn + wn + ni * 8 + tg * 2;
#pragma unroll
                for (int hr = 0; hr < 2; hr++) {
                    int row = bm + wm + mi * 16 + g + hr * 8;
                    *(float2*)&dst[(size_t)row * DD + col] =
                        make_float2(acc[mi][ni][hr * 2 + 0], acc[mi][ni][hr * 2 + 1]);
                }
            }
    }

    // last-arriver reduction (threadFenceReduction; self-resetting counter)
    {
        __shared__ int s_last;
        __syncthreads();
        if (tid == 0) {
            __threadfence();
            int old = atomicAdd(&g_cnt2[tile], 1);
            s_last = (old == 7);
            if (s_last) atomicExch(&g_cnt2[tile], 0);
        }
        __syncthreads();
        if (!s_last) {
            cudaTriggerProgrammaticLaunchCompletion();  // no further global writes
            return;
        }
        if (tid == 0) __threadfence();
        __syncthreads();
    }

    // combine + RK4 epilogue (128 thr x 32 elems over the 64x64 tile)
    const float inv6 = 1.0f / 6.0f;
#pragma unroll
    for (int q = 0; q < 4; q++) {
        int row = bm + (tid >> 3) + q * 16;
        int col = bn + (tid & 7) * 8;
        size_t off = (size_t)row * DD + col;
        float dt = __ldg(tarr + (size_t)(s + 1) * BB + row)
                 - __ldg(tarr + (size_t)s * BB + row);

        float sum[8];
        {
            float4 a = *(const float4*)&g_p2[0][off];
            float4 b = *(const float4*)&g_p2[0][off + 4];
            sum[0] = a.x; sum[1] = a.y; sum[2] = a.z; sum[3] = a.w;
            sum[4] = b.x; sum[5] = b.y; sum[6] = b.z; sum[7] = b.w;
        }
#pragma unroll
        for (int z = 1; z < 8; z++) {
            float4 a = *(const float4*)&g_p2[z][off];
            float4 b = *(const float4*)&g_p2[z][off + 4];
            sum[0] += a.x; sum[1] += a.y; sum[2] += a.z; sum[3] += a.w;
            sum[4] += b.x; sum[5] += b.y; sum[6] += b.z; sum[7] += b.w;
        }

        float kv[8];
#pragma unroll
        for (int e = 0; e < 8; e++)
            kv[e] = dt * (sum[e] + __ldg(b2 + col + e));

        float yc[8], av[8];
        *(float4*)&yc[0] = *(const float4*)&g_ycur[off];
        *(float4*)&yc[4] = *(const float4*)&g_ycur[off + 4];
        if (first) {
#pragma unroll
            for (int e = 0; e < 8; e++) av[e] = wgt * kv[e];
        } else {
            *(float4*)&av[0] = *(const float4*)&g_acc[off];
            *(float4*)&av[4] = *(const float4*)&g_acc[off + 4];
#pragma unroll
            for (int e = 0; e < 8; e++) av[e] += wgt * kv[e];
        }

        uint4 ah;
        if (!last) {
            *(float4*)&g_acc[off]     = *(const float4*)&av[0];
            *(float4*)&g_acc[off + 4] = *(const float4*)&av[4];
            __half2 h;
            h = __floats2half2_rn(yc[0] + cnext * kv[0], yc[1] + cnext * kv[1]);
            __builtin_memcpy(&ah.x, &h, 4);
            h = __floats2half2_rn(yc[2] + cnext * kv[2], yc[3] + cnext * kv[3]);
            __builtin_memcpy(&ah.y, &h, 4);
            h = __floats2half2_rn(yc[4] + cnext * kv[4], yc[5] + cnext * kv[5]);
            __builtin_memcpy(&ah.z, &h, 4);
            h = __floats2half2_rn(yc[6] + cnext * kv[6], yc[7] + cnext * kv[7]);
            __builtin_memcpy(&ah.w, &h, 4);
        } else {
            float yn[8];
#pragma unroll
            for (int e = 0; e < 8; e++) yn[e] = yc[e] + av[e] * inv6;
            *(float4*)&g_ycur[off]     = *(const float4*)&yn[0];
            *(float4*)&g_ycur[off + 4] = *(const float4*)&yn[4];
            *(float4*)&out[(size_t)(s + 1) * BB * DD + off]     = *(const float4*)&yn[0];
            *(float4*)&out[(size_t)(s + 1) * BB * DD + off + 4] = *(const float4*)&yn[4];
            __half2 h;
            h = __floats2half2_rn(yn[0], yn[1]); __builtin_memcpy(&ah.x, &h, 4);
            h = __floats2half2_rn(yn[2], yn[3]); __builtin_memcpy(&ah.y, &h, 4);
            h = __floats2half2_rn(yn[4], yn[5]); __builtin_memcpy(&ah.z, &h, 4);
            h = __floats2half2_rn(yn[6], yn[7]); __builtin_memcpy(&ah.w, &h, 4);
        }
        *(uint4*)&g_a[off] = ah;
    }
    // all global writes done -> release the dependent kernel.
    cudaTriggerProgrammaticLaunchCompletion();
}

// ---------------------------------------------------------------------------
extern "C" void kernel_launch(void* const* d_in, const int* in_sizes, int n_in,
                              void* d_out, int out_size) {
    const float* y0 = (const float*)d_in[0];
    const float* t  = (const float*)d_in[1];
    const float* W1 = (const float*)d_in[2];
    const float* b1 = (const float*)d_in[3];
    const float* W2 = (const float*)d_in[4];
    const float* b2 = (const float*)d_in[5];
    float* out = (float*)d_out;

    cudaFuncSetAttribute(gemm1_kernel, cudaFuncAttributeMaxDynamicSharedMemorySize, SMEM1);
    cudaFuncSetAttribute(gemm2_kernel, cudaFuncAttributeMaxDynamicSharedMemorySize, SMEM2);

    __half* w1h; cudaGetSymbolAddress((void**)&w1h, g_W1h);
    __half* w2h; cudaGetSymbolAddress((void**)&w2h, g_W2h);

    init_state<<<(BB * DD / 4) / 256, 256>>>(y0, out);
    convert_w<<<(DD * HH / 4) / 256, 256>>>(W1, w1h);
    convert_w<<<(HH * DD / 4) / 256, 256>>>(W2, w2h);

    const float ws[4] = {1.0f, 2.0f, 2.0f, 1.0f};
    const float cn[4] = {0.5f, 0.5f, 1.0f, 0.0f};

    dim3 grid1(HH / 128, BB / 64);     // 16 x 8 = 128 CTAs
    dim3 grid2(DD / 64, BB / 64, 8);   // 8 x 8 x 8 = 512 CTAs

    cudaLaunchAttribute pdl[1];
    pdl[0].id = cudaLaunchAttributeProgrammaticStreamSerialization;
    pdl[0].val.programmaticStreamSerializationAllowed = 1;

    cudaLaunchConfig_t cfg1 = {};
    cfg1.gridDim = grid1; cfg1.blockDim = dim3(512, 1, 1);
    cfg1.dynamicSmemBytes = SMEM1;
    cfg1.attrs = pdl; cfg1.numAttrs = 1;

    cudaLaunchConfig_t cfg2 = {};
    cfg2.gridDim = grid2; cfg2.blockDim = dim3(128, 1, 1);
    cfg2.dynamicSmemBytes = SMEM2;
    cfg2.attrs = pdl; cfg2.numAttrs = 1;

    for (int s = 0; s < TT - 1; ++s) {
        for (int i = 0; i < 4; ++i) {
            if (s == 0 && i == 0) {
                // first gemm1: producer convert_w writes W1h (read in the
                // PRE-sync prologue) -> must launch fully serialized.
                gemm1_kernel<<<grid1, 512, SMEM1>>>(b1);
            } else {
                cudaLaunchKernelEx(&cfg1, gemm1_kernel, b1);
            }
            cudaLaunchKernelEx(&cfg2, gemm2_kernel, b2, t, out, s, ws[i], cn[i],
                               (i == 0) ? 1 : 0, (i == 3) ? 1 : 0);
        }
    }
}